// round 14
// baseline (speedup 1.0000x reference)
#include <cuda_runtime.h>
#include <cuda_fp16.h>
#include <cstdint>

#define BB 32
#define CC 128
#define HH 56
#define WW 56
#define SIZE (CC*HH*WW)          // 401408
#define HW   (HH*WW)             // 3136
#define PH 58
#define PHW (PH*PH)              // 3364 padded plane
#define EPSV 1e-5f
#define SLOPE 0.1f
#define APITCH 80                 // smem row pitch bytes (5*16, odd 16B count)
#define STAGE_BYTES (2*128*APITCH)   // A + B tiles per stage = 20480
#define NSTAGE 4
#define FP 66                     // fuse1 smem pitch (halves)

// scratch (allocation-free rule: __device__ globals)
__device__ __align__(256) __half g_zh[(size_t)BB*PHW*CC]; // 27.6MB NHWC padded z
__device__ __align__(256) __half g_wth[9*CC*CC];          // [tap][oc][ic] fp16
__device__ __align__(256) float4 g_fold[SIZE];            // (ws0, ws1, sh, 0)
__device__ float  g_s2[CC];
__device__ float  g_sh2[CC];

__device__ __forceinline__ uint32_t smem_u32(const void* p) {
    uint32_t a;
    asm("{ .reg .u64 t; cvta.to.shared.u64 t, %1; cvt.u32.u64 %0, t; }"
        : "=r"(a) : "l"(p));
    return a;
}
__device__ __forceinline__ void mma_f16(float* d, const uint32_t* a,
                                        const uint32_t* b) {
    asm volatile(
        "mma.sync.aligned.m16n8k16.row.col.f32.f16.f16.f32 "
        "{%0,%1,%2,%3}, {%4,%5,%6,%7}, {%8,%9}, {%0,%1,%2,%3};"
        : "+f"(d[0]), "+f"(d[1]), "+f"(d[2]), "+f"(d[3])
        : "r"(a[0]), "r"(a[1]), "r"(a[2]), "r"(a[3]),
          "r"(b[0]), "r"(b[1]));
}
#define LDSM_X4(r0, r1, r2, r3, addr) \
    asm volatile("ldmatrix.sync.aligned.m8n8.x4.shared.b16 " \
                 "{%0,%1,%2,%3}, [%4];" \
                 : "=r"(r0), "=r"(r1), "=r"(r2), "=r"(r3) : "r"(addr))

// ---------------------------------------------------------------------------
// Setup: param fold + weight transpose + NHWC borders + epilogue params
// ---------------------------------------------------------------------------
__global__ void scrm_setup(const float* __restrict__ cfc,
                           const float* __restrict__ gamma,
                           const float* __restrict__ beta,
                           const float* __restrict__ mean,
                           const float* __restrict__ var,
                           const float* __restrict__ gw,
                           const float* __restrict__ cb,
                           const float* __restrict__ g2,
                           const float* __restrict__ b2,
                           const float* __restrict__ m2,
                           const float* __restrict__ v2) {
    int idx = blockIdx.x * 256 + threadIdx.x;
    if (idx < SIZE) {
        float s = gamma[idx] * rsqrtf(var[idx] + EPSV);
        float4 f;
        f.x = cfc[2 * idx] * s;
        f.y = cfc[2 * idx + 1] * s;
        f.z = beta[idx] - mean[idx] * s;
        f.w = 0.f;
        g_fold[idx] = f;
    }
    if (idx < 9 * CC * CC) {
        int ic = idx & 127;
        int oc = (idx >> 7) & 127;
        int t  = idx >> 14;
        g_wth[idx] = __float2half(gw[oc * 1152 + ic * 9 + t]);
    }
    if (idx < BB * 3648) {                  // zero NHWC borders, 16B per idx
        int b = idx / 3648;
        int r = idx - b * 3648;
        int off;
        if (r < 928)       off = (r >> 4) * CC + (r & 15) * 8;
        else if (r < 1856) { int q = r - 928;  off = (57 * PH + (q >> 4)) * CC + (q & 15) * 8; }
        else if (r < 2752) { int q = r - 1856; off = ((1 + (q >> 4)) * PH) * CC + (q & 15) * 8; }
        else               { int q = r - 2752; off = ((1 + (q >> 4)) * PH + 57) * CC + (q & 15) * 8; }
        uint4 z4 = {0u, 0u, 0u, 0u};
        *(uint4*)(g_zh + (size_t)b * PHW * CC + off) = z4;
    }
    if (idx < CC) {
        float s = g2[idx] * rsqrtf(v2[idx] + EPSV);
        g_s2[idx]  = s;
        g_sh2[idx] = fmaf(cb[idx] - m2[idx], s, b2[idx]);
    }
}

// ---------------------------------------------------------------------------
// Kernel 1: combine + BN1d + LeakyReLU -> fp16 NHWC padded [B][58][58][128].
// Grid (56 y, 2 c-halves, 4 b-quarters) = 448 CTAs (full chip). Folded
// params in registers; smem transpose -> coalesced NHWC writes.
// ---------------------------------------------------------------------------
__global__ void __launch_bounds__(256)
scrm_fuse1(const float* __restrict__ ax, const float* __restrict__ mx) {
    __shared__ __half zs[WW * FP];          // [x][c] pitch 66 halves

    const int t    = threadIdx.x;
    const int y    = blockIdx.x;            // 0..55
    const int coff = blockIdx.y * 64;       // c half
    const int b0   = blockIdx.z * 8;        // batch quarter

    float4 fold[14];
    int    off[14];
    int    sts[14];
#pragma unroll
    for (int j = 0; j < 14; j++) {
        int elem = t + 256 * j;             // < 3584 = 64c x 56x
        int c = elem / 56;
        int x = elem - c * 56;
        off[j] = (coff + c) * HW + y * WW + x;
        sts[j] = x * FP + c;
        fold[j] = g_fold[off[j]];
    }

    for (int b = b0; b < b0 + 8; b++) {
        const float* axb = ax + (size_t)b * SIZE;
        const float* mxb = mx + (size_t)b * SIZE;
#pragma unroll
        for (int j = 0; j < 14; j++) {
            float a = __ldg(axb + off[j]);
            float m = __ldg(mxb + off[j]);
            float z = fmaf(fold[j].x, a, fmaf(fold[j].y, m, fold[j].z));
            z = (z > 0.f) ? z : SLOPE * z;
            zs[sts[j]] = __float2half(z);
        }
        __syncthreads();
        __half* orow = g_zh + ((size_t)b * PHW + (y + 1) * PH + 1) * CC + coff;
#pragma unroll
        for (int m2 = 0; m2 < 2; m2++) {
            int idx = t + 256 * m2;
            if (idx < 448) {                // 56 px x 8 segs(16B) of this half
                int px = idx >> 3, seg = idx & 7;
                const uint32_t* zp = (const uint32_t*)
                    ((const char*)zs + px * (FP * 2) + seg * 16);
                uint4 v;
                v.x = zp[0]; v.y = zp[1]; v.z = zp[2]; v.w = zp[3];
                *(uint4*)(orow + (size_t)px * CC + seg * 8) = v;
            }
        }
        __syncthreads();
    }
}

// ---------------------------------------------------------------------------
// Kernel 2: fp16 mma.sync implicit-GEMM conv, 4-stage cp.async pipeline.
// CTA: 256 thr (8 warps, 2 M x 4 N), block 128 px x 128 oc, K-chunk 32.
// 36 stages (9 taps x 4 c-chunks), prefetch depth 3, ONE barrier per stage
// (WAR safe: prefetch(s+3) runs after top-of-s barrier, which proves all
// warps finished compute(s-1) on that buffer). Pitch 80B = odd 16B count.
// ---------------------------------------------------------------------------
__global__ void __launch_bounds__(256, 2)
scrm_conv_mma(float* __restrict__ out) {
    extern __shared__ unsigned char smem[];   // NSTAGE x (A + B)

    const int tid  = threadIdx.x;
    const int wid  = tid >> 5;
    const int lane = tid & 31;
    const int warp_m = wid >> 2;    // 0..1
    const int warp_n = wid & 3;     // 0..3
    const int g    = lane >> 2;     // 0..7
    const int tig  = lane & 3;      // 0..3

    // A-copy role: one pixel per thread (px = tid>>1), 2 x 16B segs
    const int px   = tid >> 1;
    const int half16 = (tid & 1) * 16;        // halves offset within 64-ch chunk
    const __half* aptr;
    {
        int gp = blockIdx.x * 128 + px;
        int b  = gp / HW;
        int p  = gp - b * HW;
        int yy = p / WW, xx = p - (p / WW) * WW;
        aptr = g_zh + ((size_t)b * PHW + (yy + 1) * PH + (xx + 1)) * CC;
    }

    // ldmatrix lane-constant addressing (layout verified in R12/R13)
    const int rA   = warp_m * 64 + (lane & 15);
    const int rB   = warp_n * 32 + (lane & 15);
    const int csel = (lane >> 4) * 16;

    float acc[4][4][4];
#pragma unroll
    for (int mi = 0; mi < 4; mi++)
#pragma unroll
        for (int ni = 0; ni < 4; ni++)
#pragma unroll
            for (int j = 0; j < 4; j++) acc[mi][ni][j] = 0.f;

    auto prefetch = [&](int s) {
        unsigned char* As = smem + (s & (NSTAGE - 1)) * STAGE_BYTES;
        unsigned char* Bs = As + 128 * APITCH;
        const int tap = s >> 2;
        const int c0  = (s & 3) * 32;             // halves
        const int t3  = tap / 3;
        const int doff = ((t3 - 1) * PH + (tap - 3 * t3 - 1)) * CC + c0;
        // A: px row, 2 segs of 16B (this thread's half16 window: halves 0-15)
        const uint32_t dA = smem_u32(As) + px * APITCH + (tid & 1) * 32;
        const __half* sA_src = aptr + doff + half16;
        asm volatile("cp.async.ca.shared.global [%0], [%1], 16;"
            :: "r"(dA), "l"(sA_src));
        asm volatile("cp.async.ca.shared.global [%0], [%1], 16;"
            :: "r"(dA + 16), "l"(sA_src + 8));
        // B: oc row = px, same seg split
        const __half* wb = g_wth + (size_t)tap * (CC * CC) + c0
                         + (size_t)px * CC + half16;
        const uint32_t dB = smem_u32(Bs) + px * APITCH + (tid & 1) * 32;
        asm volatile("cp.async.ca.shared.global [%0], [%1], 16;"
            :: "r"(dB), "l"(wb));
        asm volatile("cp.async.ca.shared.global [%0], [%1], 16;"
            :: "r"(dB + 16), "l"(wb + 8));
        asm volatile("cp.async.commit_group;" ::: "memory");
    };

    prefetch(0);
    prefetch(1);
    prefetch(2);

    for (int s = 0; s < 36; ++s) {
        asm volatile("cp.async.wait_group 2;" ::: "memory");
        __syncthreads();                          // stage s visible to all

        const uint32_t Abase =
            smem_u32(smem + (s & (NSTAGE - 1)) * STAGE_BYTES);
        const uint32_t Bbase = Abase + 128 * APITCH;
#pragma unroll
        for (int ks = 0; ks < 2; ks++) {
            const int cb = ks * 32 + csel;
            uint32_t afr[4][4], bt[2][4];
#pragma unroll
            for (int mi = 0; mi < 4; mi++)
                LDSM_X4(afr[mi][0], afr[mi][1], afr[mi][2], afr[mi][3],
                        Abase + (rA + mi * 16) * APITCH + cb);
#pragma unroll
            for (int nj = 0; nj < 2; nj++)
                LDSM_X4(bt[nj][0], bt[nj][1], bt[nj][2], bt[nj][3],
                        Bbase + (rB + nj * 16) * APITCH + cb);
#pragma unroll
            for (int mi = 0; mi < 4; mi++) {
#pragma unroll
                for (int ni = 0; ni < 4; ni++) {
                    uint32_t bfr[2] = { bt[ni >> 1][ni & 1],
                                        bt[ni >> 1][(ni & 1) + 2] };
                    mma_f16(acc[mi][ni], afr[mi], bfr);
                }
            }
        }
        if (s + 3 < 36) prefetch(s + 3);
        else asm volatile("cp.async.commit_group;" ::: "memory");
    }

    // ---- epilogue: bias+BN2d+LeakyReLU, scatter to NCHW out ----
#pragma unroll
    for (int mi = 0; mi < 4; mi++) {
#pragma unroll
        for (int half = 0; half < 2; half++) {
            int row = warp_m * 64 + mi * 16 + g + half * 8;
            int gpo = blockIdx.x * 128 + row;
            int bo  = gpo / HW;
            int po  = gpo - bo * HW;
            float* obase = out + (size_t)bo * SIZE + po;
#pragma unroll
            for (int ni = 0; ni < 4; ni++) {
#pragma unroll
                for (int jj = 0; jj < 2; jj++) {
                    int oc = warp_n * 32 + ni * 8 + 2 * tig + jj;
                    float v = fmaf(acc[mi][ni][half * 2 + jj],
                                   __ldg(&g_s2[oc]), __ldg(&g_sh2[oc]));
                    obase[(size_t)oc * HW] = (v > 0.f) ? v : SLOPE * v;
                }
            }
        }
    }
}

// ---------------------------------------------------------------------------
// launch
// ---------------------------------------------------------------------------
extern "C" void kernel_launch(void* const* d_in, const int* in_sizes, int n_in,
                              void* d_out, int out_size) {
    const float* ax   = (const float*)d_in[0];
    const float* mx   = (const float*)d_in[1];
    const float* cfc  = (const float*)d_in[2];
    const float* bng  = (const float*)d_in[3];
    const float* bnb  = (const float*)d_in[4];
    const float* bnm  = (const float*)d_in[5];
    const float* bnv  = (const float*)d_in[6];
    const float* cw   = (const float*)d_in[7];
    const float* cb   = (const float*)d_in[8];
    const float* g2   = (const float*)d_in[9];
    const float* b2   = (const float*)d_in[10];
    const float* m2   = (const float*)d_in[11];
    const float* v2   = (const float*)d_in[12];
    float* out = (float*)d_out;

    cudaFuncSetAttribute(scrm_conv_mma,
                         cudaFuncAttributeMaxDynamicSharedMemorySize,
                         NSTAGE * STAGE_BYTES);

    scrm_setup<<<(SIZE + 255) / 256, 256>>>(cfc, bng, bnb, bnm, bnv,
                                            cw, cb, g2, b2, m2, v2);
    dim3 fgrid(HH, 2, 4);
    scrm_fuse1<<<fgrid, 256>>>(ax, mx);
    scrm_conv_mma<<<BB * HW / 128, 256, NSTAGE * STAGE_BYTES>>>(out);
}

// round 15
// speedup vs baseline: 1.1470x; 1.1470x over previous
#include <cuda_runtime.h>
#include <cuda_fp16.h>
#include <cstdint>

#define BB 32
#define CC 128
#define HH 56
#define WW 56
#define SIZE (CC*HH*WW)          // 401408
#define HW   (HH*WW)             // 3136
#define PH 58
#define PHW (PH*PH)              // 3364 padded plane
#define EPSV 1e-5f
#define SLOPE 0.1f
#define APITCH 144                // conv smem row pitch bytes (9*16, odd 16B count)
#define STAGE_BYTES (2*128*APITCH)   // A + B tiles per stage = 36864
#define FP 66                     // fuse1 smem pitch (halves)

// scratch (allocation-free rule: __device__ globals)
__device__ __align__(256) __half g_zh[(size_t)BB*PHW*CC]; // 27.6MB NHWC padded z
__device__ __align__(256) __half g_wth[9*CC*CC];          // [tap][oc][ic] fp16
__device__ __align__(256) float4 g_fold[SIZE];            // (ws0, ws1, sh, 0)
__device__ float  g_s2[CC];
__device__ float  g_sh2[CC];

__device__ __forceinline__ uint32_t smem_u32(const void* p) {
    uint32_t a;
    asm("{ .reg .u64 t; cvta.to.shared.u64 t, %1; cvt.u32.u64 %0, t; }"
        : "=r"(a) : "l"(p));
    return a;
}
__device__ __forceinline__ void mma_f16(float* d, const uint32_t* a,
                                        const uint32_t* b) {
    asm volatile(
        "mma.sync.aligned.m16n8k16.row.col.f32.f16.f16.f32 "
        "{%0,%1,%2,%3}, {%4,%5,%6,%7}, {%8,%9}, {%0,%1,%2,%3};"
        : "+f"(d[0]), "+f"(d[1]), "+f"(d[2]), "+f"(d[3])
        : "r"(a[0]), "r"(a[1]), "r"(a[2]), "r"(a[3]),
          "r"(b[0]), "r"(b[1]));
}
#define LDSM_X4(r0, r1, r2, r3, addr) \
    asm volatile("ldmatrix.sync.aligned.m8n8.x4.shared.b16 " \
                 "{%0,%1,%2,%3}, [%4];" \
                 : "=r"(r0), "=r"(r1), "=r"(r2), "=r"(r3) : "r"(addr))

// ---------------------------------------------------------------------------
// Setup: param fold + weight transpose + NHWC borders + epilogue params
// ---------------------------------------------------------------------------
__global__ void scrm_setup(const float* __restrict__ cfc,
                           const float* __restrict__ gamma,
                           const float* __restrict__ beta,
                           const float* __restrict__ mean,
                           const float* __restrict__ var,
                           const float* __restrict__ gw,
                           const float* __restrict__ cb,
                           const float* __restrict__ g2,
                           const float* __restrict__ b2,
                           const float* __restrict__ m2,
                           const float* __restrict__ v2) {
    int idx = blockIdx.x * 256 + threadIdx.x;
    if (idx < SIZE) {
        float s = gamma[idx] * rsqrtf(var[idx] + EPSV);
        float4 f;
        f.x = cfc[2 * idx] * s;
        f.y = cfc[2 * idx + 1] * s;
        f.z = beta[idx] - mean[idx] * s;
        f.w = 0.f;
        g_fold[idx] = f;
    }
    if (idx < 9 * CC * CC) {
        int ic = idx & 127;
        int oc = (idx >> 7) & 127;
        int t  = idx >> 14;
        g_wth[idx] = __float2half(gw[oc * 1152 + ic * 9 + t]);
    }
    if (idx < BB * 3648) {                  // zero NHWC borders, 16B per idx
        int b = idx / 3648;
        int r = idx - b * 3648;
        int off;
        if (r < 928)       off = (r >> 4) * CC + (r & 15) * 8;
        else if (r < 1856) { int q = r - 928;  off = (57 * PH + (q >> 4)) * CC + (q & 15) * 8; }
        else if (r < 2752) { int q = r - 1856; off = ((1 + (q >> 4)) * PH) * CC + (q & 15) * 8; }
        else               { int q = r - 2752; off = ((1 + (q >> 4)) * PH + 57) * CC + (q & 15) * 8; }
        uint4 z4 = {0u, 0u, 0u, 0u};
        *(uint4*)(g_zh + (size_t)b * PHW * CC + off) = z4;
    }
    if (idx < CC) {
        float s = g2[idx] * rsqrtf(v2[idx] + EPSV);
        g_s2[idx]  = s;
        g_sh2[idx] = fmaf(cb[idx] - m2[idx], s, b2[idx]);
    }
}

// ---------------------------------------------------------------------------
// Kernel 1: combine + BN1d + LeakyReLU -> fp16 NHWC padded [B][58][58][128].
// Grid (56 y, 2 c-halves, 4 b-quarters) = 448 CTAs (full chip). Folded
// params in registers; smem transpose -> coalesced NHWC writes.
// ---------------------------------------------------------------------------
__global__ void __launch_bounds__(256)
scrm_fuse1(const float* __restrict__ ax, const float* __restrict__ mx) {
    __shared__ __half zs[WW * FP];          // [x][c] pitch 66 halves

    const int t    = threadIdx.x;
    const int y    = blockIdx.x;            // 0..55
    const int coff = blockIdx.y * 64;       // c half
    const int b0   = blockIdx.z * 8;        // batch quarter

    float4 fold[14];
    int    off[14];
    int    sts[14];
#pragma unroll
    for (int j = 0; j < 14; j++) {
        int elem = t + 256 * j;             // < 3584 = 64c x 56x
        int c = elem / 56;
        int x = elem - c * 56;
        off[j] = (coff + c) * HW + y * WW + x;
        sts[j] = x * FP + c;
        fold[j] = g_fold[off[j]];
    }

    for (int b = b0; b < b0 + 8; b++) {
        const float* axb = ax + (size_t)b * SIZE;
        const float* mxb = mx + (size_t)b * SIZE;
#pragma unroll
        for (int j = 0; j < 14; j++) {
            float a = __ldg(axb + off[j]);
            float m = __ldg(mxb + off[j]);
            float z = fmaf(fold[j].x, a, fmaf(fold[j].y, m, fold[j].z));
            z = (z > 0.f) ? z : SLOPE * z;
            zs[sts[j]] = __float2half(z);
        }
        __syncthreads();
        __half* orow = g_zh + ((size_t)b * PHW + (y + 1) * PH + 1) * CC + coff;
#pragma unroll
        for (int m2 = 0; m2 < 2; m2++) {
            int idx = t + 256 * m2;
            if (idx < 448) {                // 56 px x 8 segs(16B) of this half
                int px = idx >> 3, seg = idx & 7;
                const uint32_t* zp = (const uint32_t*)
                    ((const char*)zs + px * (FP * 2) + seg * 16);
                uint4 v;
                v.x = zp[0]; v.y = zp[1]; v.z = zp[2]; v.w = zp[3];
                *(uint4*)(orow + (size_t)px * CC + seg * 8) = v;
            }
        }
        __syncthreads();
    }
}

// ---------------------------------------------------------------------------
// Kernel 2: fp16 mma.sync implicit-GEMM conv (R13 measured-best structure).
// CTA: 256 thr (8 warps, 2 M x 4 N), block 128 px x 128 oc, K-chunk 64.
// 18 stages (9 taps x 2 c-chunks), 2-stage cp.async buffer, two barriers
// per stage. Pitch 144B (odd 16B count): cp.async dst and non-trans
// ldmatrix both conflict-free.
// ---------------------------------------------------------------------------
__global__ void __launch_bounds__(256, 2)
scrm_conv_mma(float* __restrict__ out) {
    extern __shared__ unsigned char smem[];   // 2 stages x (A + B)

    const int tid  = threadIdx.x;
    const int wid  = tid >> 5;
    const int lane = tid & 31;
    const int warp_m = wid >> 2;    // 0..1
    const int warp_n = wid & 3;     // 0..3
    const int g    = lane >> 2;     // 0..7
    const int tig  = lane & 3;      // 0..3

    // per-thread A-copy roles: 4 pixels (tid>>3 + 32q), seg = tid&7
    const __half* aptr[4];
#pragma unroll
    for (int q = 0; q < 4; q++) {
        int px = (tid >> 3) + 32 * q;
        int gp = blockIdx.x * 128 + px;
        int b  = gp / HW;
        int p  = gp - b * HW;
        int yy = p / WW, xx = p - (p / WW) * WW;
        aptr[q] = g_zh + ((size_t)b * PHW + (yy + 1) * PH + (xx + 1)) * CC;
    }

    // ldmatrix lane-constant addressing (layout verified R12/R13)
    const int rA   = warp_m * 64 + (lane & 15);   // + mi*16 rows
    const int rB   = warp_n * 32 + (lane & 15);   // + nj*16 rows
    const int csel = (lane >> 4) * 16;            // byte col select

    float acc[4][4][4];
#pragma unroll
    for (int mi = 0; mi < 4; mi++)
#pragma unroll
        for (int ni = 0; ni < 4; ni++)
#pragma unroll
            for (int j = 0; j < 4; j++) acc[mi][ni][j] = 0.f;

    auto prefetch = [&](int s) {
        unsigned char* As = smem + (s & 1) * STAGE_BYTES;
        unsigned char* Bs = As + 128 * APITCH;
        const int tap = s >> 1;
        const int c0  = (s & 1) * 64;             // halves
        const int t3  = tap / 3;
        const int doff = ((t3 - 1) * PH + (tap - 3 * t3 - 1)) * CC + c0;
        const uint32_t dA = smem_u32(As) + (tid >> 3) * APITCH + (tid & 7) * 16;
#pragma unroll
        for (int q = 0; q < 4; q++) {
            asm volatile("cp.async.ca.shared.global [%0], [%1], 16;"
                :: "r"(dA + (uint32_t)(32 * q * APITCH)),
                   "l"(aptr[q] + doff + (tid & 7) * 8));
        }
        const __half* wb = g_wth + (size_t)tap * (CC * CC) + c0;
        const uint32_t dB = smem_u32(Bs);
#pragma unroll
        for (int q = 0; q < 4; q++) {
            int idx = tid + 256 * q;              // 0..1023
            int oc = idx >> 3, sg = idx & 7;
            asm volatile("cp.async.ca.shared.global [%0], [%1], 16;"
                :: "r"(dB + oc * APITCH + sg * 16),
                   "l"(wb + (size_t)oc * CC + sg * 8));
        }
        asm volatile("cp.async.commit_group;" ::: "memory");
    };

    prefetch(0);
    for (int s = 0; s < 18; ++s) {
        if (s + 1 < 18) {
            prefetch(s + 1);
            asm volatile("cp.async.wait_group 1;" ::: "memory");
        } else {
            asm volatile("cp.async.wait_group 0;" ::: "memory");
        }
        __syncthreads();                          // stage s data ready

        const uint32_t Abase = smem_u32(smem + (s & 1) * STAGE_BYTES);
        const uint32_t Bbase = Abase + 128 * APITCH;
#pragma unroll
        for (int ks = 0; ks < 4; ks++) {
            const int cb = ks * 32 + csel;
            uint32_t afr[4][4], bt[2][4];
#pragma unroll
            for (int mi = 0; mi < 4; mi++)
                LDSM_X4(afr[mi][0], afr[mi][1], afr[mi][2], afr[mi][3],
                        Abase + (rA + mi * 16) * APITCH + cb);
#pragma unroll
            for (int nj = 0; nj < 2; nj++)
                LDSM_X4(bt[nj][0], bt[nj][1], bt[nj][2], bt[nj][3],
                        Bbase + (rB + nj * 16) * APITCH + cb);
#pragma unroll
            for (int mi = 0; mi < 4; mi++) {
#pragma unroll
                for (int ni = 0; ni < 4; ni++) {
                    uint32_t bfr[2] = { bt[ni >> 1][ni & 1],
                                        bt[ni >> 1][(ni & 1) + 2] };
                    mma_f16(acc[mi][ni], afr[mi], bfr);
                }
            }
        }
        __syncthreads();                          // WAR before next prefetch
    }

    // ---- epilogue: bias+BN2d+LeakyReLU, scatter to NCHW out ----
#pragma unroll
    for (int mi = 0; mi < 4; mi++) {
#pragma unroll
        for (int half = 0; half < 2; half++) {
            int row = warp_m * 64 + mi * 16 + g + half * 8;
            int gpo = blockIdx.x * 128 + row;
            int bo  = gpo / HW;
            int po  = gpo - bo * HW;
            float* obase = out + (size_t)bo * SIZE + po;
#pragma unroll
            for (int ni = 0; ni < 4; ni++) {
#pragma unroll
                for (int jj = 0; jj < 2; jj++) {
                    int oc = warp_n * 32 + ni * 8 + 2 * tig + jj;
                    float v = fmaf(acc[mi][ni][half * 2 + jj],
                                   __ldg(&g_s2[oc]), __ldg(&g_sh2[oc]));
                    obase[(size_t)oc * HW] = (v > 0.f) ? v : SLOPE * v;
                }
            }
        }
    }
}

// ---------------------------------------------------------------------------
// launch
// ---------------------------------------------------------------------------
extern "C" void kernel_launch(void* const* d_in, const int* in_sizes, int n_in,
                              void* d_out, int out_size) {
    const float* ax   = (const float*)d_in[0];
    const float* mx   = (const float*)d_in[1];
    const float* cfc  = (const float*)d_in[2];
    const float* bng  = (const float*)d_in[3];
    const float* bnb  = (const float*)d_in[4];
    const float* bnm  = (const float*)d_in[5];
    const float* bnv  = (const float*)d_in[6];
    const float* cw   = (const float*)d_in[7];
    const float* cb   = (const float*)d_in[8];
    const float* g2   = (const float*)d_in[9];
    const float* b2   = (const float*)d_in[10];
    const float* m2   = (const float*)d_in[11];
    const float* v2   = (const float*)d_in[12];
    float* out = (float*)d_out;

    cudaFuncSetAttribute(scrm_conv_mma,
                         cudaFuncAttributeMaxDynamicSharedMemorySize,
                         2 * STAGE_BYTES);

    scrm_setup<<<(SIZE + 255) / 256, 256>>>(cfc, bng, bnb, bnm, bnv,
                                            cw, cb, g2, b2, m2, v2);
    dim3 fgrid(HH, 2, 4);
    scrm_fuse1<<<fgrid, 256>>>(ax, mx);
    scrm_conv_mma<<<BB * HW / 128, 256, 2 * STAGE_BYTES>>>(out);
}